// round 2
// baseline (speedup 1.0000x reference)
#include <cuda_runtime.h>
#include <cuda_bf16.h>
#include <cstdint>

#define GEMM_GRID 296
#define BSZ       128
#define DEL       196608          // 3*256*256
#define KC        64              // K elements per chunk
#define NCHUNK    (DEL / KC)      // 3072
#define REGP      0.01f
#define NUM_ITER  100
#define SW        36              // smem row stride in uint32 words (72 bf16)

// -------- deterministic global scratch (no allocations allowed) --------
__device__ float g_P [GEMM_GRID][BSZ * BSZ]; // split-K partial dot products
__device__ float g_xp[GEMM_GRID][BSZ];       // partial ||delta||^2
__device__ float g_yp[GEMM_GRID][BSZ];       // partial ||target||^2
__device__ float g_x2[BSZ];
__device__ float g_y2[BSZ];
__device__ float g_C [BSZ * BSZ];            // cost matrix

__device__ __forceinline__ uint32_t pack_bf16x2(float lo, float hi) {
    __nv_bfloat162 h = __floats2bfloat162_rn(lo, hi);
    return *reinterpret_cast<uint32_t*>(&h);
}

// ============================================================
// Kernel 1: split-K GEMM (bf16 HMMA) + fp32 row norms
//   A = imgs_w - imgs  [128, DEL],  B = target [128, DEL]
//   P[cta][i][j] += sum_k A[i][k]*B[j][k] over this CTA's K-chunks
// ============================================================
__global__ void __launch_bounds__(256, 2)
gemm_kernel(const float* __restrict__ imgs,
            const float* __restrict__ imgsw,
            const float* __restrict__ tgt)
{
    __shared__ uint32_t sA[BSZ * SW];   // bf16 pairs, k-contiguous, stride 36 words
    __shared__ uint32_t sB[BSZ * SW];

    const int tid  = threadIdx.x;
    const int lane = tid & 31;
    const int warp = tid >> 5;
    const int r    = tid >> 1;          // row this thread loads (2 threads/row)
    const int h    = tid & 1;           // which half of the 64-col chunk

    const int m0 = (warp & 3) * 32;     // warp's M offset in C
    const int n0 = (warp >> 2) * 64;    // warp's N offset in C
    const int g  = lane >> 2;           // mma groupID
    const int tg = lane & 3;            // mma thread-in-group

    float acc[2][8][4];
    #pragma unroll
    for (int a = 0; a < 2; a++)
        #pragma unroll
        for (int b = 0; b < 8; b++)
            #pragma unroll
            for (int cidx = 0; cidx < 4; cidx++) acc[a][b][cidx] = 0.f;

    float sx = 0.f, sy = 0.f;

    for (int c = blockIdx.x; c < NCHUNK; c += GEMM_GRID) {
        __syncthreads();   // protect smem from previous iteration's mma reads

        const size_t rowbase = (size_t)r * DEL + (size_t)c * KC;
        const float4* pi = reinterpret_cast<const float4*>(imgs  + rowbase);
        const float4* pw = reinterpret_cast<const float4*>(imgsw + rowbase);
        const float4* pt = reinterpret_cast<const float4*>(tgt   + rowbase);

        #pragma unroll
        for (int j = 0; j < 8; j++) {
            const int f = h * 8 + j;            // float4 index 0..15 in the row
            float4 a4 = pi[f];
            float4 w4 = pw[f];
            float4 d4 = make_float4(w4.x - a4.x, w4.y - a4.y,
                                    w4.z - a4.z, w4.w - a4.w);
            sx += d4.x * d4.x + d4.y * d4.y + d4.z * d4.z + d4.w * d4.w;
            sA[r * SW + f * 2    ] = pack_bf16x2(d4.x, d4.y);
            sA[r * SW + f * 2 + 1] = pack_bf16x2(d4.z, d4.w);

            float4 t4 = pt[f];
            sy += t4.x * t4.x + t4.y * t4.y + t4.z * t4.z + t4.w * t4.w;
            sB[r * SW + f * 2    ] = pack_bf16x2(t4.x, t4.y);
            sB[r * SW + f * 2 + 1] = pack_bf16x2(t4.z, t4.w);
        }
        __syncthreads();

        // 4 K-steps of 16 over this 64-wide chunk
        #pragma unroll
        for (int kk = 0; kk < 4; kk++) {
            uint32_t A0[2], A1[2], A2[2], A3[2];
            #pragma unroll
            for (int mt = 0; mt < 2; mt++) {
                const int row = m0 + mt * 16 + g;
                A0[mt] = sA[ row      * SW + kk * 8 + tg    ];
                A1[mt] = sA[(row + 8) * SW + kk * 8 + tg    ];
                A2[mt] = sA[ row      * SW + kk * 8 + tg + 4];
                A3[mt] = sA[(row + 8) * SW + kk * 8 + tg + 4];
            }
            #pragma unroll
            for (int nt = 0; nt < 8; nt++) {
                const int nrow = n0 + nt * 8 + g;
                uint32_t b0 = sB[nrow * SW + kk * 8 + tg    ];
                uint32_t b1 = sB[nrow * SW + kk * 8 + tg + 4];
                #pragma unroll
                for (int mt = 0; mt < 2; mt++) {
                    asm volatile(
                        "mma.sync.aligned.m16n8k16.row.col.f32.bf16.bf16.f32 "
                        "{%0,%1,%2,%3}, {%4,%5,%6,%7}, {%8,%9}, {%0,%1,%2,%3};"
                        : "+f"(acc[mt][nt][0]), "+f"(acc[mt][nt][1]),
                          "+f"(acc[mt][nt][2]), "+f"(acc[mt][nt][3])
                        : "r"(A0[mt]), "r"(A1[mt]), "r"(A2[mt]), "r"(A3[mt]),
                          "r"(b0), "r"(b1));
                }
            }
        }
    }

    // write split-K partials
    float* P = g_P[blockIdx.x];
    #pragma unroll
    for (int mt = 0; mt < 2; mt++) {
        #pragma unroll
        for (int nt = 0; nt < 8; nt++) {
            const int row = m0 + mt * 16 + g;
            const int col = n0 + nt * 8 + tg * 2;
            float2* p0 = reinterpret_cast<float2*>(&P[ row      * BSZ + col]);
            float2* p1 = reinterpret_cast<float2*>(&P[(row + 8) * BSZ + col]);
            *p0 = make_float2(acc[mt][nt][0], acc[mt][nt][1]);
            *p1 = make_float2(acc[mt][nt][2], acc[mt][nt][3]);
        }
    }

    // norm partials: the two threads of a row are adjacent lanes
    sx += __shfl_xor_sync(0xFFFFFFFFu, sx, 1);
    sy += __shfl_xor_sync(0xFFFFFFFFu, sy, 1);
    if (h == 0) {
        g_xp[blockIdx.x][r] = sx;
        g_yp[blockIdx.x][r] = sy;
    }
}

// ============================================================
// Kernel 2: reduce norm partials
// ============================================================
__global__ void norm_reduce_kernel()
{
    const int t = threadIdx.x;
    float sx = 0.f, sy = 0.f;
    #pragma unroll 4
    for (int c = 0; c < GEMM_GRID; c++) {
        sx += g_xp[c][t];
        sy += g_yp[c][t];
    }
    g_x2[t] = sx;
    g_y2[t] = sy;
}

// ============================================================
// Kernel 3: reduce split-K partials, build C = sqrt(max(x2+y2-2xy,0))
// ============================================================
__global__ void cost_kernel()
{
    const int i = blockIdx.x;
    const int j = threadIdx.x;
    float s = 0.f;
    #pragma unroll 4
    for (int c = 0; c < GEMM_GRID; c++)
        s += g_P[c][i * BSZ + j];
    const float sq = g_x2[i] + g_y2[j] - 2.f * s;
    g_C[i * BSZ + j] = sqrtf(fmaxf(sq, 0.f));
}

// ============================================================
// Kernel 4: 100 Sinkhorn iterations, single CTA, 512 threads.
//   Register-resident E = exp(C - rowmax), Et = exp(C^T - colmax);
//   each half-pass is a 128x128 matvec on the FMA pipe.
//   lse_j(C - u_i - v_j) = -u_i + M_i + log( sum_j E_ij * exp(-v_j) )
// ============================================================
__global__ void __launch_bounds__(512, 1)
sinkhorn_kernel(float* __restrict__ out)
{
    __shared__ float u[BSZ], v[BSZ], w[BSZ], eu[BSZ];

    const int t = threadIdx.x;
    const int r = t >> 2;     // row (and column, for the transpose pass)
    const int q = t & 3;      // quarter: owns 32 elements

    const float LOGA = -4.852030263919617f;   // log(1/128)

    // ---- setup: row fragment E[32] = exp(C[r][q*32+k] - rowmax) ----
    float E[32], Et[32];
    float mrow = -1e30f;
    {
        const float4* c4p = reinterpret_cast<const float4*>(g_C + r * BSZ + q * 32);
        #pragma unroll
        for (int k4 = 0; k4 < 8; k4++) {
            float4 c4 = c4p[k4];
            E[k4 * 4 + 0] = c4.x; E[k4 * 4 + 1] = c4.y;
            E[k4 * 4 + 2] = c4.z; E[k4 * 4 + 3] = c4.w;
            mrow = fmaxf(mrow, fmaxf(fmaxf(c4.x, c4.y), fmaxf(c4.z, c4.w)));
        }
    }
    mrow = fmaxf(mrow, __shfl_xor_sync(0xFFFFFFFFu, mrow, 1));
    mrow = fmaxf(mrow, __shfl_xor_sync(0xFFFFFFFFu, mrow, 2));
    #pragma unroll
    for (int k = 0; k < 32; k++) E[k] = __expf(E[k] - mrow);

    // ---- setup: column fragment Et[32] = exp(C[q*32+k][r] - colmax) ----
    float mcol = -1e30f;
    #pragma unroll
    for (int k = 0; k < 32; k++) {
        float cv = g_C[(q * 32 + k) * BSZ + r];
        Et[k] = cv;
        mcol = fmaxf(mcol, cv);
    }
    mcol = fmaxf(mcol, __shfl_xor_sync(0xFFFFFFFFu, mcol, 1));
    mcol = fmaxf(mcol, __shfl_xor_sync(0xFFFFFFFFu, mcol, 2));
    #pragma unroll
    for (int k = 0; k < 32; k++) Et[k] = __expf(Et[k] - mcol);

    if (t < BSZ) { u[t] = 0.f; v[t] = 0.f; }
    __syncthreads();

    for (int it = 0; it < NUM_ITER; it++) {
        // -------- u update (lse over j) --------
        if (t < BSZ) w[t] = __expf(-v[t]);
        __syncthreads();

        float S = 0.f;
        {
            const float4* w4 = reinterpret_cast<const float4*>(w + q * 32);
            #pragma unroll
            for (int k4 = 0; k4 < 8; k4++) {
                float4 ww = w4[k4];
                S += E[k4 * 4 + 0] * ww.x + E[k4 * 4 + 1] * ww.y
                   + E[k4 * 4 + 2] * ww.z + E[k4 * 4 + 3] * ww.w;
            }
        }
        S += __shfl_xor_sync(0xFFFFFFFFu, S, 1);
        S += __shfl_xor_sync(0xFFFFFFFFu, S, 2);
        const float un = REGP * (LOGA + u[r] - mrow - __logf(S));
        if (q == 0) { u[r] = un; eu[r] = __expf(-un); }
        __syncthreads();

        // -------- v update (lse over i), uses updated u --------
        float T = 0.f;
        {
            const float4* e4 = reinterpret_cast<const float4*>(eu + q * 32);
            #pragma unroll
            for (int k4 = 0; k4 < 8; k4++) {
                float4 ee = e4[k4];
                T += Et[k4 * 4 + 0] * ee.x + Et[k4 * 4 + 1] * ee.y
                   + Et[k4 * 4 + 2] * ee.z + Et[k4 * 4 + 3] * ee.w;
            }
        }
        T += __shfl_xor_sync(0xFFFFFFFFu, T, 1);
        T += __shfl_xor_sync(0xFFFFFFFFu, T, 2);
        const float vn = REGP * (LOGA + v[r] - mcol - __logf(T));
        if (q == 0) v[r] = vn;
        __syncthreads();
    }

    // out = sum(u*a + v*b) = (sum u + sum v) / 128
    if (t == 0) {
        float s = 0.f;
        for (int i = 0; i < BSZ; i++) s += u[i] + v[i];
        out[0] = s * (1.0f / BSZ);
    }
}

// ============================================================
extern "C" void kernel_launch(void* const* d_in, const int* in_sizes, int n_in,
                              void* d_out, int out_size)
{
    const float* imgs  = (const float*)d_in[0];
    const float* imgsw = (const float*)d_in[1];
    const float* tgt   = (const float*)d_in[2];
    float* out = (float*)d_out;

    gemm_kernel<<<GEMM_GRID, 256>>>(imgs, imgsw, tgt);
    norm_reduce_kernel<<<1, BSZ>>>();
    cost_kernel<<<BSZ, BSZ>>>();
    sinkhorn_kernel<<<1, 512>>>(out);
}

// round 3
// speedup vs baseline: 1.1554x; 1.1554x over previous
#include <cuda_runtime.h>
#include <cuda_bf16.h>
#include <cstdint>

#define GEMM_GRID 296
#define BSZ       128
#define DEL       196608          // 3*256*256
#define KC        32              // K elements per chunk
#define NCHUNK    (DEL / KC)      // 6144
#define REGP      0.01f
#define NUM_ITER  100
#define SW        20              // smem row stride in uint32 words (40 bf16)

// -------- deterministic global scratch (no allocations allowed) --------
__device__ float g_P [GEMM_GRID][BSZ * BSZ]; // split-K partial dot products
__device__ float g_xp[GEMM_GRID][BSZ];       // partial ||delta||^2
__device__ float g_yp[GEMM_GRID][BSZ];       // partial ||target||^2
__device__ float g_x2[BSZ];
__device__ float g_y2[BSZ];
__device__ float g_C [BSZ * BSZ];            // cost matrix

__device__ __forceinline__ uint32_t pack_bf16x2(float lo, float hi) {
    __nv_bfloat162 h = __floats2bfloat162_rn(lo, hi);
    return *reinterpret_cast<uint32_t*>(&h);
}

// ============================================================
// Kernel 1: split-K GEMM (bf16 HMMA) + fp32 row norms
//   Double-buffered smem pipeline, dense 128B-per-row coalesced loads.
//   A = imgs_w - imgs [128, DEL], B = target [128, DEL]
// ============================================================
__global__ void __launch_bounds__(256, 2)
gemm_kernel(const float* __restrict__ imgs,
            const float* __restrict__ imgsw,
            const float* __restrict__ tgt)
{
    __shared__ uint32_t sA[2][BSZ * SW];
    __shared__ uint32_t sB[2][BSZ * SW];

    const int tid  = threadIdx.x;
    const int lane = tid & 31;
    const int warp = tid >> 5;

    // loader mapping: 8 lanes cover one row's 128B (one K=32 chunk) densely
    const int g8 = lane >> 3;       // row-in-quad 0..3
    const int f  = lane & 7;        // float4 index within the row chunk

    // mma mapping: 4x2 warp grid over the 128x128 C tile
    const int m0 = (warp & 3) * 32;
    const int n0 = (warp >> 2) * 64;
    const int g  = lane >> 2;
    const int tg = lane & 3;

    float acc[2][8][4];
    #pragma unroll
    for (int a = 0; a < 2; a++)
        #pragma unroll
        for (int b = 0; b < 8; b++)
            #pragma unroll
            for (int cc = 0; cc < 4; cc++) acc[a][b][cc] = 0.f;

    float sx[4] = {0.f, 0.f, 0.f, 0.f};
    float sy[4] = {0.f, 0.f, 0.f, 0.f};

    // load one K=32 chunk into stage st, accumulating norm partials
    auto load_chunk = [&](int c, int st) {
        #pragma unroll
        for (int k = 0; k < 4; k++) {
            const int row = warp * 4 + g8 + 32 * k;       // 0..127
            const size_t fidx = (size_t)row * (DEL / 4) + (size_t)c * 8 + f;
            float4 a4 = reinterpret_cast<const float4*>(imgs )[fidx];
            float4 w4 = reinterpret_cast<const float4*>(imgsw)[fidx];
            float4 t4 = reinterpret_cast<const float4*>(tgt  )[fidx];
            float4 d4 = make_float4(w4.x - a4.x, w4.y - a4.y,
                                    w4.z - a4.z, w4.w - a4.w);
            sx[k] += d4.x * d4.x + d4.y * d4.y + d4.z * d4.z + d4.w * d4.w;
            sy[k] += t4.x * t4.x + t4.y * t4.y + t4.z * t4.z + t4.w * t4.w;
            sA[st][row * SW + f * 2    ] = pack_bf16x2(d4.x, d4.y);
            sA[st][row * SW + f * 2 + 1] = pack_bf16x2(d4.z, d4.w);
            sB[st][row * SW + f * 2    ] = pack_bf16x2(t4.x, t4.y);
            sB[st][row * SW + f * 2 + 1] = pack_bf16x2(t4.z, t4.w);
        }
    };

    int st = 0;
    load_chunk(blockIdx.x, 0);

    for (int c = blockIdx.x; c < NCHUNK; c += GEMM_GRID) {
        __syncthreads();                 // stage st ready; previous mma done
        const int cn = c + GEMM_GRID;
        if (cn < NCHUNK) load_chunk(cn, st ^ 1);   // LDGs overlap the mma below

        #pragma unroll
        for (int kk = 0; kk < 2; kk++) {
            uint32_t A0[2], A1[2], A2[2], A3[2];
            #pragma unroll
            for (int mt = 0; mt < 2; mt++) {
                const int row = m0 + mt * 16 + g;
                A0[mt] = sA[st][ row      * SW + kk * 8 + tg    ];
                A1[mt] = sA[st][(row + 8) * SW + kk * 8 + tg    ];
                A2[mt] = sA[st][ row      * SW + kk * 8 + tg + 4];
                A3[mt] = sA[st][(row + 8) * SW + kk * 8 + tg + 4];
            }
            #pragma unroll
            for (int nt = 0; nt < 8; nt++) {
                const int nrow = n0 + nt * 8 + g;
                uint32_t b0 = sB[st][nrow * SW + kk * 8 + tg    ];
                uint32_t b1 = sB[st][nrow * SW + kk * 8 + tg + 4];
                #pragma unroll
                for (int mt = 0; mt < 2; mt++) {
                    asm volatile(
                        "mma.sync.aligned.m16n8k16.row.col.f32.bf16.bf16.f32 "
                        "{%0,%1,%2,%3}, {%4,%5,%6,%7}, {%8,%9}, {%0,%1,%2,%3};"
                        : "+f"(acc[mt][nt][0]), "+f"(acc[mt][nt][1]),
                          "+f"(acc[mt][nt][2]), "+f"(acc[mt][nt][3])
                        : "r"(A0[mt]), "r"(A1[mt]), "r"(A2[mt]), "r"(A3[mt]),
                          "r"(b0), "r"(b1));
                }
            }
        }
        st ^= 1;
    }

    // write split-K partials
    float* P = g_P[blockIdx.x];
    #pragma unroll
    for (int mt = 0; mt < 2; mt++) {
        #pragma unroll
        for (int nt = 0; nt < 8; nt++) {
            const int row = m0 + mt * 16 + g;
            const int col = n0 + nt * 8 + tg * 2;
            float2* p0 = reinterpret_cast<float2*>(&P[ row      * BSZ + col]);
            float2* p1 = reinterpret_cast<float2*>(&P[(row + 8) * BSZ + col]);
            *p0 = make_float2(acc[mt][nt][0], acc[mt][nt][1]);
            *p1 = make_float2(acc[mt][nt][2], acc[mt][nt][3]);
        }
    }

    // norm partials: 8 lanes (same g8 group) share a row
    #pragma unroll
    for (int k = 0; k < 4; k++) {
        float x = sx[k], y = sy[k];
        x += __shfl_xor_sync(0xFFFFFFFFu, x, 1);
        x += __shfl_xor_sync(0xFFFFFFFFu, x, 2);
        x += __shfl_xor_sync(0xFFFFFFFFu, x, 4);
        y += __shfl_xor_sync(0xFFFFFFFFu, y, 1);
        y += __shfl_xor_sync(0xFFFFFFFFu, y, 2);
        y += __shfl_xor_sync(0xFFFFFFFFu, y, 4);
        if (f == 0) {
            const int row = warp * 4 + g8 + 32 * k;
            g_xp[blockIdx.x][row] = x;
            g_yp[blockIdx.x][row] = y;
        }
    }
}

// ============================================================
// Kernel 2: reduce norm partials
// ============================================================
__global__ void norm_reduce_kernel()
{
    const int t = threadIdx.x;
    float sxv = 0.f, syv = 0.f;
    #pragma unroll 4
    for (int c = 0; c < GEMM_GRID; c++) {
        sxv += g_xp[c][t];
        syv += g_yp[c][t];
    }
    g_x2[t] = sxv;
    g_y2[t] = syv;
}

// ============================================================
// Kernel 3: reduce split-K partials, build C
// ============================================================
__global__ void cost_kernel()
{
    const int i = blockIdx.x;
    const int j = threadIdx.x;
    float s = 0.f;
    #pragma unroll 4
    for (int c = 0; c < GEMM_GRID; c++)
        s += g_P[c][i * BSZ + j];
    const float sq = g_x2[i] + g_y2[j] - 2.f * s;
    g_C[i * BSZ + j] = sqrtf(fmaxf(sq, 0.f));
}

// ============================================================
// Kernel 4: 100 Sinkhorn iterations, single CTA, 512 threads.
//   eu/ev maintained in smem (2 barriers/iter); 4-acc ILP matvec.
//   lse_j(C - u_i - v_j) = -u_i + M_i + log( sum_j E_ij * exp(-v_j) )
// ============================================================
__global__ void __launch_bounds__(512, 1)
sinkhorn_kernel(float* __restrict__ out)
{
    __shared__ float u[BSZ], v[BSZ], eu[BSZ], ev[BSZ];
    __shared__ float red[16];

    const int t = threadIdx.x;
    const int r = t >> 2;     // row (u-phase) / column (v-phase)
    const int q = t & 3;      // quarter: owns 32 elements

    const float LOGA = -4.852030263919617f;   // log(1/128)

    // ---- setup: E[32] = exp(C[r][q*32+k] - rowmax) ----
    float E[32], Et[32];
    float mrow = -1e30f;
    {
        const float4* c4p = reinterpret_cast<const float4*>(g_C + r * BSZ + q * 32);
        #pragma unroll
        for (int k4 = 0; k4 < 8; k4++) {
            float4 c4 = c4p[k4];
            E[k4 * 4 + 0] = c4.x; E[k4 * 4 + 1] = c4.y;
            E[k4 * 4 + 2] = c4.z; E[k4 * 4 + 3] = c4.w;
            mrow = fmaxf(mrow, fmaxf(fmaxf(c4.x, c4.y), fmaxf(c4.z, c4.w)));
        }
    }
    mrow = fmaxf(mrow, __shfl_xor_sync(0xFFFFFFFFu, mrow, 1));
    mrow = fmaxf(mrow, __shfl_xor_sync(0xFFFFFFFFu, mrow, 2));
    #pragma unroll
    for (int k = 0; k < 32; k++) E[k] = __expf(E[k] - mrow);

    // ---- setup: Et[32] = exp(C[q*32+k][r] - colmax) ----
    float mcol = -1e30f;
    #pragma unroll
    for (int k = 0; k < 32; k++) {
        float cv = g_C[(q * 32 + k) * BSZ + r];
        Et[k] = cv;
        mcol = fmaxf(mcol, cv);
    }
    mcol = fmaxf(mcol, __shfl_xor_sync(0xFFFFFFFFu, mcol, 1));
    mcol = fmaxf(mcol, __shfl_xor_sync(0xFFFFFFFFu, mcol, 2));
    #pragma unroll
    for (int k = 0; k < 32; k++) Et[k] = __expf(Et[k] - mcol);

    if (t < BSZ) { u[t] = 0.f; v[t] = 0.f; eu[t] = 1.f; ev[t] = 1.f; }
    __syncthreads();

    for (int it = 0; it < NUM_ITER; it++) {
        // -------- u update: S_r = sum_j E[r][j] * ev[j] --------
        {
            float s0 = 0.f, s1 = 0.f, s2 = 0.f, s3 = 0.f;
            const float4* e4 = reinterpret_cast<const float4*>(ev + q * 32);
            #pragma unroll
            for (int k4 = 0; k4 < 8; k4++) {
                float4 w = e4[k4];
                s0 = fmaf(E[k4 * 4 + 0], w.x, s0);
                s1 = fmaf(E[k4 * 4 + 1], w.y, s1);
                s2 = fmaf(E[k4 * 4 + 2], w.z, s2);
                s3 = fmaf(E[k4 * 4 + 3], w.w, s3);
            }
            float S = (s0 + s1) + (s2 + s3);
            S += __shfl_xor_sync(0xFFFFFFFFu, S, 1);
            S += __shfl_xor_sync(0xFFFFFFFFu, S, 2);
            const float un = REGP * (LOGA + u[r] - mrow - __logf(S));
            if (q == 0) { u[r] = un; eu[r] = __expf(-un); }
        }
        __syncthreads();

        // -------- v update: T_r = sum_i Et[r][i] * eu[i] --------
        {
            float s0 = 0.f, s1 = 0.f, s2 = 0.f, s3 = 0.f;
            const float4* e4 = reinterpret_cast<const float4*>(eu + q * 32);
            #pragma unroll
            for (int k4 = 0; k4 < 8; k4++) {
                float4 w = e4[k4];
                s0 = fmaf(Et[k4 * 4 + 0], w.x, s0);
                s1 = fmaf(Et[k4 * 4 + 1], w.y, s1);
                s2 = fmaf(Et[k4 * 4 + 2], w.z, s2);
                s3 = fmaf(Et[k4 * 4 + 3], w.w, s3);
            }
            float T = (s0 + s1) + (s2 + s3);
            T += __shfl_xor_sync(0xFFFFFFFFu, T, 1);
            T += __shfl_xor_sync(0xFFFFFFFFu, T, 2);
            const float vn = REGP * (LOGA + v[r] - mcol - __logf(T));
            if (q == 0) { v[r] = vn; ev[r] = __expf(-vn); }
        }
        __syncthreads();
    }

    // parallel final reduction: out = (sum u + sum v) / 128
    float s = (t < BSZ) ? (u[t] + v[t]) : 0.f;
    #pragma unroll
    for (int o = 16; o > 0; o >>= 1)
        s += __shfl_xor_sync(0xFFFFFFFFu, s, o);
    if ((t & 31) == 0) red[t >> 5] = s;
    __syncthreads();
    if (t == 0)
        out[0] = (red[0] + red[1] + red[2] + red[3]) * (1.0f / BSZ);
}

// ============================================================
extern "C" void kernel_launch(void* const* d_in, const int* in_sizes, int n_in,
                              void* d_out, int out_size)
{
    const float* imgs  = (const float*)d_in[0];
    const float* imgsw = (const float*)d_in[1];
    const float* tgt   = (const float*)d_in[2];
    float* out = (float*)d_out;

    gemm_kernel<<<GEMM_GRID, 256>>>(imgs, imgsw, tgt);
    norm_reduce_kernel<<<1, BSZ>>>();
    cost_kernel<<<BSZ, BSZ>>>();
    sinkhorn_kernel<<<1, 512>>>(out);
}

// round 5
// speedup vs baseline: 3.1150x; 2.6959x over previous
#include <cuda_runtime.h>
#include <cuda_bf16.h>
#include <cstdint>

#define GEMM_GRID 296
#define BSZ       128
#define DEL       196608          // 3*256*256
#define KC        32              // K elements per chunk
#define NCHUNK    (DEL / KC)      // 6144
#define REGP      0.01f
#define NUM_ITER  100
#define SW        20              // smem row stride in uint32 words (40 bf16)

// -------- deterministic global scratch (no allocations allowed) --------
__device__ float g_P [GEMM_GRID][BSZ * BSZ]; // split-K partial dot products
__device__ float g_xp[GEMM_GRID][BSZ];       // partial ||delta||^2
__device__ float g_yp[GEMM_GRID][BSZ];       // partial ||target||^2
__device__ float g_x2[BSZ];
__device__ float g_y2[BSZ];
__device__ float g_C [BSZ * BSZ];            // cost matrix

__device__ __forceinline__ uint32_t pack_bf16x2(float lo, float hi) {
    __nv_bfloat162 h = __floats2bfloat162_rn(lo, hi);
    return *reinterpret_cast<uint32_t*>(&h);
}

// ============================================================
// Kernel 1: split-K GEMM (bf16 HMMA) + fp32 row norms
// ============================================================
__global__ void __launch_bounds__(256, 2)
gemm_kernel(const float* __restrict__ imgs,
            const float* __restrict__ imgsw,
            const float* __restrict__ tgt)
{
    __shared__ uint32_t sA[2][BSZ * SW];
    __shared__ uint32_t sB[2][BSZ * SW];

    const int tid  = threadIdx.x;
    const int lane = tid & 31;
    const int warp = tid >> 5;

    // loader mapping: 8 lanes cover one row's 128B (one K=32 chunk) densely
    const int g8 = lane >> 3;       // row-in-quad 0..3
    const int f  = lane & 7;        // float4 index within the row chunk

    // mma mapping: 4x2 warp grid over the 128x128 C tile
    const int m0 = (warp & 3) * 32;
    const int n0 = (warp >> 2) * 64;
    const int g  = lane >> 2;
    const int tg = lane & 3;

    float acc[2][8][4];
    #pragma unroll
    for (int a = 0; a < 2; a++)
        #pragma unroll
        for (int b = 0; b < 8; b++)
            #pragma unroll
            for (int cc = 0; cc < 4; cc++) acc[a][b][cc] = 0.f;

    float sx[4] = {0.f, 0.f, 0.f, 0.f};
    float sy[4] = {0.f, 0.f, 0.f, 0.f};

    auto load_chunk = [&](int c, int st) {
        #pragma unroll
        for (int k = 0; k < 4; k++) {
            const int row = warp * 4 + g8 + 32 * k;       // 0..127
            const size_t fidx = (size_t)row * (DEL / 4) + (size_t)c * 8 + f;
            float4 a4 = reinterpret_cast<const float4*>(imgs )[fidx];
            float4 w4 = reinterpret_cast<const float4*>(imgsw)[fidx];
            float4 t4 = reinterpret_cast<const float4*>(tgt  )[fidx];
            float4 d4 = make_float4(w4.x - a4.x, w4.y - a4.y,
                                    w4.z - a4.z, w4.w - a4.w);
            sx[k] += d4.x * d4.x + d4.y * d4.y + d4.z * d4.z + d4.w * d4.w;
            sy[k] += t4.x * t4.x + t4.y * t4.y + t4.z * t4.z + t4.w * t4.w;
            sA[st][row * SW + f * 2    ] = pack_bf16x2(d4.x, d4.y);
            sA[st][row * SW + f * 2 + 1] = pack_bf16x2(d4.z, d4.w);
            sB[st][row * SW + f * 2    ] = pack_bf16x2(t4.x, t4.y);
            sB[st][row * SW + f * 2 + 1] = pack_bf16x2(t4.z, t4.w);
        }
    };

    int st = 0;
    load_chunk(blockIdx.x, 0);

    for (int c = blockIdx.x; c < NCHUNK; c += GEMM_GRID) {
        __syncthreads();
        const int cn = c + GEMM_GRID;
        if (cn < NCHUNK) load_chunk(cn, st ^ 1);

        #pragma unroll
        for (int kk = 0; kk < 2; kk++) {
            uint32_t A0[2], A1[2], A2[2], A3[2];
            #pragma unroll
            for (int mt = 0; mt < 2; mt++) {
                const int row = m0 + mt * 16 + g;
                A0[mt] = sA[st][ row      * SW + kk * 8 + tg    ];
                A1[mt] = sA[st][(row + 8) * SW + kk * 8 + tg    ];
                A2[mt] = sA[st][ row      * SW + kk * 8 + tg + 4];
                A3[mt] = sA[st][(row + 8) * SW + kk * 8 + tg + 4];
            }
            #pragma unroll
            for (int nt = 0; nt < 8; nt++) {
                const int nrow = n0 + nt * 8 + g;
                uint32_t b0 = sB[st][nrow * SW + kk * 8 + tg    ];
                uint32_t b1 = sB[st][nrow * SW + kk * 8 + tg + 4];
                #pragma unroll
                for (int mt = 0; mt < 2; mt++) {
                    asm volatile(
                        "mma.sync.aligned.m16n8k16.row.col.f32.bf16.bf16.f32 "
                        "{%0,%1,%2,%3}, {%4,%5,%6,%7}, {%8,%9}, {%0,%1,%2,%3};"
                        : "+f"(acc[mt][nt][0]), "+f"(acc[mt][nt][1]),
                          "+f"(acc[mt][nt][2]), "+f"(acc[mt][nt][3])
                        : "r"(A0[mt]), "r"(A1[mt]), "r"(A2[mt]), "r"(A3[mt]),
                          "r"(b0), "r"(b1));
                }
            }
        }
        st ^= 1;
    }

    float* P = g_P[blockIdx.x];
    #pragma unroll
    for (int mt = 0; mt < 2; mt++) {
        #pragma unroll
        for (int nt = 0; nt < 8; nt++) {
            const int row = m0 + mt * 16 + g;
            const int col = n0 + nt * 8 + tg * 2;
            float2* p0 = reinterpret_cast<float2*>(&P[ row      * BSZ + col]);
            float2* p1 = reinterpret_cast<float2*>(&P[(row + 8) * BSZ + col]);
            *p0 = make_float2(acc[mt][nt][0], acc[mt][nt][1]);
            *p1 = make_float2(acc[mt][nt][2], acc[mt][nt][3]);
        }
    }

    #pragma unroll
    for (int k = 0; k < 4; k++) {
        float x = sx[k], y = sy[k];
        x += __shfl_xor_sync(0xFFFFFFFFu, x, 1);
        x += __shfl_xor_sync(0xFFFFFFFFu, x, 2);
        x += __shfl_xor_sync(0xFFFFFFFFu, x, 4);
        y += __shfl_xor_sync(0xFFFFFFFFu, y, 1);
        y += __shfl_xor_sync(0xFFFFFFFFu, y, 2);
        y += __shfl_xor_sync(0xFFFFFFFFu, y, 4);
        if (f == 0) {
            const int row = warp * 4 + g8 + 32 * k;
            g_xp[blockIdx.x][row] = x;
            g_yp[blockIdx.x][row] = y;
        }
    }
}

// ============================================================
// Kernel 2: reduce norm partials
// ============================================================
__global__ void norm_reduce_kernel()
{
    const int t = threadIdx.x;
    float sxv = 0.f, syv = 0.f;
    #pragma unroll 4
    for (int c = 0; c < GEMM_GRID; c++) {
        sxv += g_xp[c][t];
        syv += g_yp[c][t];
    }
    g_x2[t] = sxv;
    g_y2[t] = syv;
}

// ============================================================
// Kernel 3: reduce split-K partials, build C
// ============================================================
__global__ void cost_kernel()
{
    const int i = blockIdx.x;
    const int j = threadIdx.x;
    float s = 0.f;
    #pragma unroll 4
    for (int c = 0; c < GEMM_GRID; c++)
        s += g_P[c][i * BSZ + j];
    const float sq = g_x2[i] + g_y2[j] - 2.f * s;
    g_C[i * BSZ + j] = sqrtf(fmaxf(sq, 0.f));
}

// ============================================================
// Kernel 4: Sinkhorn, single CTA, 512 threads.
//   Group = 4 lanes (q=0..3) per row/column r = t>>2.
//   - E/Et fragments in registers (exp(C - rowmax/colmax))
//   - exp(-u), exp(-v) published via pad-indexed smem (conflict-free:
//     e[j + 4*(j>>5)] puts the 4 q-bases at banks 4q+4k)
//   - u,v kept in registers (all 4 lanes redundantly; consistent since
//     S is butterfly-broadcast). No branches: all lanes store the same
//     value to the same smem address (coalesced same-address STS).
//   - fixed-point early exit via __syncthreads_and (free: replaces the
//     barriers we need anyway).
// ============================================================
__global__ void __launch_bounds__(512, 1)
sinkhorn_kernel(float* __restrict__ out)
{
    __shared__ __align__(16) float evp[144];   // padded exp(-v)
    __shared__ __align__(16) float eup[144];   // padded exp(-u)
    __shared__ float up[BSZ], vp[BSZ];
    __shared__ float red[16];

    const int t    = threadIdx.x;
    const int lane = t & 31;
    const int q    = lane & 3;
    const int r    = t >> 2;
    const int sidx = r + ((r >> 5) << 2);      // pad-index for publishing

    const float LOGA = -4.852030263919617f;    // log(1/128)
    const float K2   = REGP * 0.6931471805599453f;  // REG * ln2

    // ---- setup: E[32] = exp(C[r][q*32+k] - rowmax) ----
    float E[32], Et[32];
    float mrow = -1e30f;
    {
        const float4* c4p = reinterpret_cast<const float4*>(g_C + r * BSZ + q * 32);
        #pragma unroll
        for (int k4 = 0; k4 < 8; k4++) {
            float4 c4 = c4p[k4];
            E[k4 * 4 + 0] = c4.x; E[k4 * 4 + 1] = c4.y;
            E[k4 * 4 + 2] = c4.z; E[k4 * 4 + 3] = c4.w;
            mrow = fmaxf(mrow, fmaxf(fmaxf(c4.x, c4.y), fmaxf(c4.z, c4.w)));
        }
    }
    mrow = fmaxf(mrow, __shfl_xor_sync(0xFFFFFFFFu, mrow, 1));
    mrow = fmaxf(mrow, __shfl_xor_sync(0xFFFFFFFFu, mrow, 2));
    #pragma unroll
    for (int k = 0; k < 32; k++) E[k] = __expf(E[k] - mrow);

    // ---- setup: Et[32] = exp(C[q*32+k][r] - colmax) ----
    float mcol = -1e30f;
    #pragma unroll
    for (int k = 0; k < 32; k++) {
        float cv = g_C[(q * 32 + k) * BSZ + r];
        Et[k] = cv;
        mcol = fmaxf(mcol, cv);
    }
    mcol = fmaxf(mcol, __shfl_xor_sync(0xFFFFFFFFu, mcol, 1));
    mcol = fmaxf(mcol, __shfl_xor_sync(0xFFFFFFFFu, mcol, 2));
    #pragma unroll
    for (int k = 0; k < 32; k++) Et[k] = __expf(Et[k] - mcol);

    // per-group folded constants: un = REG*u + cu - K2*log2(S)
    const float cu = REGP * (LOGA - mrow);
    const float cv = REGP * (LOGA - mcol);

    float ureg = 0.f, vreg = 0.f;

    if (t < 144) { evp[t] = 1.f; eup[t] = 1.f; }
    __syncthreads();

    const float4* evq = reinterpret_cast<const float4*>(evp + q * 36);
    const float4* euq = reinterpret_cast<const float4*>(eup + q * 36);

    bool done = false;
    for (int it = 0; it < NUM_ITER && !done; ++it) {
        // -------- u update: S_r = sum_j E[r][j] * exp(-v_j) --------
        float s0 = 0.f, s1 = 0.f, s2 = 0.f, s3 = 0.f;
        #pragma unroll
        for (int k4 = 0; k4 < 8; k4++) {
            float4 w = evq[k4];
            s0 = fmaf(E[k4 * 4 + 0], w.x, s0);
            s1 = fmaf(E[k4 * 4 + 1], w.y, s1);
            s2 = fmaf(E[k4 * 4 + 2], w.z, s2);
            s3 = fmaf(E[k4 * 4 + 3], w.w, s3);
        }
        float S = (s0 + s1) + (s2 + s3);
        S += __shfl_xor_sync(0xFFFFFFFFu, S, 1);
        S += __shfl_xor_sync(0xFFFFFFFFu, S, 2);
        float un = fmaf(REGP, ureg, cu) - K2 * __log2f(S);
        eup[sidx] = __expf(-un);           // all 4 lanes, same value/addr
        float du = fabsf(un - ureg);
        ureg = un;
        int convu = __syncthreads_and(du < 2.5e-7f);

        // -------- v update: T_r = sum_i Et[r][i] * exp(-u_i) --------
        float t0 = 0.f, t1 = 0.f, t2 = 0.f, t3 = 0.f;
        #pragma unroll
        for (int k4 = 0; k4 < 8; k4++) {
            float4 w = euq[k4];
            t0 = fmaf(Et[k4 * 4 + 0], w.x, t0);
            t1 = fmaf(Et[k4 * 4 + 1], w.y, t1);
            t2 = fmaf(Et[k4 * 4 + 2], w.z, t2);
            t3 = fmaf(Et[k4 * 4 + 3], w.w, t3);
        }
        float T = (t0 + t1) + (t2 + t3);
        T += __shfl_xor_sync(0xFFFFFFFFu, T, 1);
        T += __shfl_xor_sync(0xFFFFFFFFu, T, 2);
        float vn = fmaf(REGP, vreg, cv) - K2 * __log2f(T);
        evp[sidx] = __expf(-vn);           // all 4 lanes, same value/addr
        float dv = fabsf(vn - vreg);
        vreg = vn;
        int convv = __syncthreads_and(dv < 2.5e-7f);

        done = (it >= 11) && (convu != 0) && (convv != 0);
    }

    // out = (sum u + sum v) / 128
    up[r] = ureg;                          // redundant same-value stores
    vp[r] = vreg;
    __syncthreads();
    float s = (t < BSZ) ? (up[t] + vp[t]) : 0.f;
    #pragma unroll
    for (int o = 16; o > 0; o >>= 1)
        s += __shfl_xor_sync(0xFFFFFFFFu, s, o);
    if (lane == 0) red[t >> 5] = s;
    __syncthreads();
    if (t == 0)
        out[0] = (red[0] + red[1] + red[2] + red[3]) * (1.0f / BSZ);
}

// ============================================================
extern "C" void kernel_launch(void* const* d_in, const int* in_sizes, int n_in,
                              void* d_out, int out_size)
{
    const float* imgs  = (const float*)d_in[0];
    const float* imgsw = (const float*)d_in[1];
    const float* tgt   = (const float*)d_in[2];
    float* out = (float*)d_out;

    gemm_kernel<<<GEMM_GRID, 256>>>(imgs, imgsw, tgt);
    norm_reduce_kernel<<<1, BSZ>>>();
    cost_kernel<<<BSZ, BSZ>>>();
    sinkhorn_kernel<<<1, 512>>>(out);
}

// round 6
// speedup vs baseline: 3.8483x; 1.2354x over previous
#include <cuda_runtime.h>
#include <cuda_bf16.h>
#include <cstdint>

#define GEMM_GRID 148
#define BSZ       128
#define DEL       196608          // 3*256*256
#define KC        32              // K elements per chunk
#define NCHUNK    (DEL / KC)      // 6144
#define REGP      0.01f
#define NUM_ITER  100
#define SW        20              // smem row stride in uint32 words (40 bf16)

// -------- deterministic global scratch (no allocations allowed) --------
__device__ float g_P [GEMM_GRID][BSZ * BSZ]; // split-K partial dot products
__device__ float g_xp[GEMM_GRID][BSZ];       // partial ||delta||^2
__device__ float g_yp[GEMM_GRID][BSZ];       // partial ||target||^2
__device__ float g_x2[BSZ];
__device__ float g_y2[BSZ];
__device__ float g_C [BSZ * BSZ];            // cost matrix

__device__ __forceinline__ uint32_t pack_bf16x2(float lo, float hi) {
    __nv_bfloat162 h = __floats2bfloat162_rn(lo, hi);
    return *reinterpret_cast<uint32_t*>(&h);
}

// ============================================================
// Kernel 1: split-K GEMM (bf16 HMMA) + fp32 row norms.
//   Register-staged pipeline: LDG(next) -> MMA(current, hides DRAM
//   latency) -> BAR -> convert+STS(next) -> BAR. Single smem buffer.
// ============================================================
__global__ void __launch_bounds__(256, 1)
gemm_kernel(const float* __restrict__ imgs,
            const float* __restrict__ imgsw,
            const float* __restrict__ tgt)
{
    __shared__ uint32_t sA[BSZ * SW];
    __shared__ uint32_t sB[BSZ * SW];

    const int tid  = threadIdx.x;
    const int lane = tid & 31;
    const int warp = tid >> 5;

    // loader mapping: 8 lanes cover one row's 128B (one K=32 chunk) densely
    const int g8 = lane >> 3;       // row-in-quad 0..3
    const int f  = lane & 7;        // float4 index within the row chunk

    // mma mapping: 4x2 warp grid over the 128x128 C tile
    const int m0 = (warp & 3) * 32;
    const int n0 = (warp >> 2) * 64;
    const int g  = lane >> 2;
    const int tg = lane & 3;

    float acc[2][8][4];
    #pragma unroll
    for (int a = 0; a < 2; a++)
        #pragma unroll
        for (int b = 0; b < 8; b++)
            #pragma unroll
            for (int cc = 0; cc < 4; cc++) acc[a][b][cc] = 0.f;

    float sx[4] = {0.f, 0.f, 0.f, 0.f};
    float sy[4] = {0.f, 0.f, 0.f, 0.f};

    float4 ra[4], rw[4], rt[4];     // prefetch registers (48 floats)

    // issue the 12 LDG.128 for chunk c (no dependent use here)
    auto ldg_chunk = [&](int c) {
        #pragma unroll
        for (int k = 0; k < 4; k++) {
            const int row = warp * 4 + g8 + 32 * k;       // 0..127
            const size_t fidx = (size_t)row * (DEL / 4) + (size_t)c * 8 + f;
            ra[k] = reinterpret_cast<const float4*>(imgs )[fidx];
            rw[k] = reinterpret_cast<const float4*>(imgsw)[fidx];
            rt[k] = reinterpret_cast<const float4*>(tgt  )[fidx];
        }
    };

    // convert regs -> bf16 smem, accumulate norms
    auto sts_chunk = [&]() {
        #pragma unroll
        for (int k = 0; k < 4; k++) {
            const int row = warp * 4 + g8 + 32 * k;
            float4 d4 = make_float4(rw[k].x - ra[k].x, rw[k].y - ra[k].y,
                                    rw[k].z - ra[k].z, rw[k].w - ra[k].w);
            sx[k] += d4.x * d4.x + d4.y * d4.y + d4.z * d4.z + d4.w * d4.w;
            sy[k] += rt[k].x * rt[k].x + rt[k].y * rt[k].y
                   + rt[k].z * rt[k].z + rt[k].w * rt[k].w;
            sA[row * SW + f * 2    ] = pack_bf16x2(d4.x, d4.y);
            sA[row * SW + f * 2 + 1] = pack_bf16x2(d4.z, d4.w);
            sB[row * SW + f * 2    ] = pack_bf16x2(rt[k].x, rt[k].y);
            sB[row * SW + f * 2 + 1] = pack_bf16x2(rt[k].z, rt[k].w);
        }
    };

    // prologue: fill buffer with first chunk
    ldg_chunk(blockIdx.x);
    sts_chunk();
    __syncthreads();

    for (int c = blockIdx.x; c < NCHUNK; c += GEMM_GRID) {
        const int cn = c + GEMM_GRID;
        if (cn < NCHUNK) ldg_chunk(cn);   // in flight during the MMA below

        #pragma unroll
        for (int kk = 0; kk < 2; kk++) {
            uint32_t A0[2], A1[2], A2[2], A3[2];
            #pragma unroll
            for (int mt = 0; mt < 2; mt++) {
                const int row = m0 + mt * 16 + g;
                A0[mt] = sA[ row      * SW + kk * 8 + tg    ];
                A1[mt] = sA[(row + 8) * SW + kk * 8 + tg    ];
                A2[mt] = sA[ row      * SW + kk * 8 + tg + 4];
                A3[mt] = sA[(row + 8) * SW + kk * 8 + tg + 4];
            }
            #pragma unroll
            for (int nt = 0; nt < 8; nt++) {
                const int nrow = n0 + nt * 8 + g;
                uint32_t b0 = sB[nrow * SW + kk * 8 + tg    ];
                uint32_t b1 = sB[nrow * SW + kk * 8 + tg + 4];
                #pragma unroll
                for (int mt = 0; mt < 2; mt++) {
                    asm volatile(
                        "mma.sync.aligned.m16n8k16.row.col.f32.bf16.bf16.f32 "
                        "{%0,%1,%2,%3}, {%4,%5,%6,%7}, {%8,%9}, {%0,%1,%2,%3};"
                        : "+f"(acc[mt][nt][0]), "+f"(acc[mt][nt][1]),
                          "+f"(acc[mt][nt][2]), "+f"(acc[mt][nt][3])
                        : "r"(A0[mt]), "r"(A1[mt]), "r"(A2[mt]), "r"(A3[mt]),
                          "r"(b0), "r"(b1));
                }
            }
        }

        __syncthreads();                  // all warps done reading the buffer
        if (cn < NCHUNK) {
            sts_chunk();                  // LDG latency was hidden by the MMA
            __syncthreads();              // buffer ready for next iteration
        }
    }

    // write split-K partials
    float* P = g_P[blockIdx.x];
    #pragma unroll
    for (int mt = 0; mt < 2; mt++) {
        #pragma unroll
        for (int nt = 0; nt < 8; nt++) {
            const int row = m0 + mt * 16 + g;
            const int col = n0 + nt * 8 + tg * 2;
            float2* p0 = reinterpret_cast<float2*>(&P[ row      * BSZ + col]);
            float2* p1 = reinterpret_cast<float2*>(&P[(row + 8) * BSZ + col]);
            *p0 = make_float2(acc[mt][nt][0], acc[mt][nt][1]);
            *p1 = make_float2(acc[mt][nt][2], acc[mt][nt][3]);
        }
    }

    // norm partials: 8 lanes (same g8 group) share a row
    #pragma unroll
    for (int k = 0; k < 4; k++) {
        float x = sx[k], y = sy[k];
        x += __shfl_xor_sync(0xFFFFFFFFu, x, 1);
        x += __shfl_xor_sync(0xFFFFFFFFu, x, 2);
        x += __shfl_xor_sync(0xFFFFFFFFu, x, 4);
        y += __shfl_xor_sync(0xFFFFFFFFu, y, 1);
        y += __shfl_xor_sync(0xFFFFFFFFu, y, 2);
        y += __shfl_xor_sync(0xFFFFFFFFu, y, 4);
        if (f == 0) {
            const int row = warp * 4 + g8 + 32 * k;
            g_xp[blockIdx.x][row] = x;
            g_yp[blockIdx.x][row] = y;
        }
    }
}

// ============================================================
// Kernel 2: reduce norm partials
// ============================================================
__global__ void norm_reduce_kernel()
{
    const int t = threadIdx.x;
    float sxv = 0.f, syv = 0.f;
    #pragma unroll 4
    for (int c = 0; c < GEMM_GRID; c++) {
        sxv += g_xp[c][t];
        syv += g_yp[c][t];
    }
    g_x2[t] = sxv;
    g_y2[t] = syv;
}

// ============================================================
// Kernel 3: reduce split-K partials, build C.
//   512 threads/block: 4 sub-slices of the c-range per (i,j) for MLP.
// ============================================================
__global__ void __launch_bounds__(512, 1)
cost_kernel()
{
    __shared__ float part[3][BSZ];
    const int i = blockIdx.x;
    const int j = threadIdx.x & 127;
    const int s = threadIdx.x >> 7;            // 0..3

    float sum = 0.f;
    #pragma unroll 4
    for (int c = s; c < GEMM_GRID; c += 4)
        sum += g_P[c][i * BSZ + j];

    if (s > 0) part[s - 1][j] = sum;
    __syncthreads();
    if (s == 0) {
        sum += part[0][j] + part[1][j] + part[2][j];
        const float sq = g_x2[i] + g_y2[j] - 2.f * sum;
        g_C[i * BSZ + j] = sqrtf(fmaxf(sq, 0.f));
    }
}

// ============================================================
// Kernel 4: Sinkhorn (unchanged from R5 — 17 us, early exit)
// ============================================================
__global__ void __launch_bounds__(512, 1)
sinkhorn_kernel(float* __restrict__ out)
{
    __shared__ __align__(16) float evp[144];   // padded exp(-v)
    __shared__ __align__(16) float eup[144];   // padded exp(-u)
    __shared__ float up[BSZ], vp[BSZ];
    __shared__ float red[16];

    const int t    = threadIdx.x;
    const int lane = t & 31;
    const int q    = lane & 3;
    const int r    = t >> 2;
    const int sidx = r + ((r >> 5) << 2);      // pad-index for publishing

    const float LOGA = -4.852030263919617f;    // log(1/128)
    const float K2   = REGP * 0.6931471805599453f;  // REG * ln2

    float E[32], Et[32];
    float mrow = -1e30f;
    {
        const float4* c4p = reinterpret_cast<const float4*>(g_C + r * BSZ + q * 32);
        #pragma unroll
        for (int k4 = 0; k4 < 8; k4++) {
            float4 c4 = c4p[k4];
            E[k4 * 4 + 0] = c4.x; E[k4 * 4 + 1] = c4.y;
            E[k4 * 4 + 2] = c4.z; E[k4 * 4 + 3] = c4.w;
            mrow = fmaxf(mrow, fmaxf(fmaxf(c4.x, c4.y), fmaxf(c4.z, c4.w)));
        }
    }
    mrow = fmaxf(mrow, __shfl_xor_sync(0xFFFFFFFFu, mrow, 1));
    mrow = fmaxf(mrow, __shfl_xor_sync(0xFFFFFFFFu, mrow, 2));
    #pragma unroll
    for (int k = 0; k < 32; k++) E[k] = __expf(E[k] - mrow);

    float mcol = -1e30f;
    #pragma unroll
    for (int k = 0; k < 32; k++) {
        float cvv = g_C[(q * 32 + k) * BSZ + r];
        Et[k] = cvv;
        mcol = fmaxf(mcol, cvv);
    }
    mcol = fmaxf(mcol, __shfl_xor_sync(0xFFFFFFFFu, mcol, 1));
    mcol = fmaxf(mcol, __shfl_xor_sync(0xFFFFFFFFu, mcol, 2));
    #pragma unroll
    for (int k = 0; k < 32; k++) Et[k] = __expf(Et[k] - mcol);

    const float cu = REGP * (LOGA - mrow);
    const float cv = REGP * (LOGA - mcol);

    float ureg = 0.f, vreg = 0.f;

    if (t < 144) { evp[t] = 1.f; eup[t] = 1.f; }
    __syncthreads();

    const float4* evq = reinterpret_cast<const float4*>(evp + q * 36);
    const float4* euq = reinterpret_cast<const float4*>(eup + q * 36);

    bool done = false;
    for (int it = 0; it < NUM_ITER && !done; ++it) {
        float s0 = 0.f, s1 = 0.f, s2 = 0.f, s3 = 0.f;
        #pragma unroll
        for (int k4 = 0; k4 < 8; k4++) {
            float4 w = evq[k4];
            s0 = fmaf(E[k4 * 4 + 0], w.x, s0);
            s1 = fmaf(E[k4 * 4 + 1], w.y, s1);
            s2 = fmaf(E[k4 * 4 + 2], w.z, s2);
            s3 = fmaf(E[k4 * 4 + 3], w.w, s3);
        }
        float S = (s0 + s1) + (s2 + s3);
        S += __shfl_xor_sync(0xFFFFFFFFu, S, 1);
        S += __shfl_xor_sync(0xFFFFFFFFu, S, 2);
        float un = fmaf(REGP, ureg, cu) - K2 * __log2f(S);
        eup[sidx] = __expf(-un);
        float du = fabsf(un - ureg);
        ureg = un;
        int convu = __syncthreads_and(du < 2.5e-7f);

        float t0 = 0.f, t1 = 0.f, t2 = 0.f, t3 = 0.f;
        #pragma unroll
        for (int k4 = 0; k4 < 8; k4++) {
            float4 w = euq[k4];
            t0 = fmaf(Et[k4 * 4 + 0], w.x, t0);
            t1 = fmaf(Et[k4 * 4 + 1], w.y, t1);
            t2 = fmaf(Et[k4 * 4 + 2], w.z, t2);
            t3 = fmaf(Et[k4 * 4 + 3], w.w, t3);
        }
        float T = (t0 + t1) + (t2 + t3);
        T += __shfl_xor_sync(0xFFFFFFFFu, T, 1);
        T += __shfl_xor_sync(0xFFFFFFFFu, T, 2);
        float vn = fmaf(REGP, vreg, cv) - K2 * __log2f(T);
        evp[sidx] = __expf(-vn);
        float dv = fabsf(vn - vreg);
        vreg = vn;
        int convv = __syncthreads_and(dv < 2.5e-7f);

        done = (it >= 11) && (convu != 0) && (convv != 0);
    }

    up[r] = ureg;
    vp[r] = vreg;
    __syncthreads();
    float s = (t < BSZ) ? (up[t] + vp[t]) : 0.f;
    #pragma unroll
    for (int o = 16; o > 0; o >>= 1)
        s += __shfl_xor_sync(0xFFFFFFFFu, s, o);
    if (lane == 0) red[t >> 5] = s;
    __syncthreads();
    if (t == 0)
        out[0] = (red[0] + red[1] + red[2] + red[3]) * (1.0f / BSZ);
}

// ============================================================
extern "C" void kernel_launch(void* const* d_in, const int* in_sizes, int n_in,
                              void* d_out, int out_size)
{
    const float* imgs  = (const float*)d_in[0];
    const float* imgsw = (const float*)d_in[1];
    const float* tgt   = (const float*)d_in[2];
    float* out = (float*)d_out;

    gemm_kernel<<<GEMM_GRID, 256>>>(imgs, imgsw, tgt);
    norm_reduce_kernel<<<1, BSZ>>>();
    cost_kernel<<<BSZ, 512>>>();
    sinkhorn_kernel<<<1, 512>>>(out);
}

// round 7
// speedup vs baseline: 4.0405x; 1.0500x over previous
#include <cuda_runtime.h>
#include <cuda_bf16.h>
#include <cstdint>

#define GEMM_GRID 148
#define BSZ       128
#define DEL       196608          // 3*256*256
#define KC        32              // K elements per chunk
#define NCHUNK    (DEL / KC)      // 6144
#define REGP      0.01f
#define NUM_ITER  100
#define SW        20              // smem row stride in uint32 words (40 bf16)

// -------- deterministic global scratch (no allocations allowed) --------
__device__ float g_P [GEMM_GRID][BSZ * BSZ]; // split-K partial dot products
__device__ float g_xp[GEMM_GRID][BSZ];       // partial ||delta||^2
__device__ float g_yp[GEMM_GRID][BSZ];       // partial ||target||^2
__device__ float g_x2[BSZ];
__device__ float g_y2[BSZ];
__device__ float g_C [BSZ * BSZ];            // cost matrix

__device__ __forceinline__ uint32_t pack_bf16x2(float lo, float hi) {
    __nv_bfloat162 h = __floats2bfloat162_rn(lo, hi);
    return *reinterpret_cast<uint32_t*>(&h);
}

// ============================================================
// Kernel 1: split-K GEMM (bf16 HMMA) + fp32 row norms.
//   2-deep register prefetch + double-buffered smem:
//     iter k: LDG(k+2) ; MMA(buf[st]=chunk k) ; STS(chunk k+1 -> buf[st^1]) ; BAR
//   ~96KB/SM outstanding loads; LDG->first-use distance = 2 iterations.
// ============================================================
__global__ void __launch_bounds__(256, 1)
gemm_kernel(const float* __restrict__ imgs,
            const float* __restrict__ imgsw,
            const float* __restrict__ tgt)
{
    __shared__ uint32_t sA[2][BSZ * SW];
    __shared__ uint32_t sB[2][BSZ * SW];

    const int tid  = threadIdx.x;
    const int lane = tid & 31;
    const int warp = tid >> 5;

    // loader mapping: 8 lanes cover one row's 128B (one K=32 chunk) densely
    const int g8 = lane >> 3;       // row-in-quad 0..3
    const int f  = lane & 7;        // float4 index within the row chunk

    // mma mapping: 4x2 warp grid over the 128x128 C tile
    const int m0 = (warp & 3) * 32;
    const int n0 = (warp >> 2) * 64;
    const int g  = lane >> 2;
    const int tg = lane & 3;

    float acc[2][8][4];
    #pragma unroll
    for (int a = 0; a < 2; a++)
        #pragma unroll
        for (int b = 0; b < 8; b++)
            #pragma unroll
            for (int cc = 0; cc < 4; cc++) acc[a][b][cc] = 0.f;

    float sx[4] = {0.f, 0.f, 0.f, 0.f};
    float sy[4] = {0.f, 0.f, 0.f, 0.f};

    float4 rA0[4], rW0[4], rT0[4];      // prefetch set 0
    float4 rA1[4], rW1[4], rT1[4];      // prefetch set 1

    auto ldg_chunk = [&](int c, float4* a, float4* w, float4* t) {
        #pragma unroll
        for (int k = 0; k < 4; k++) {
            const int row = warp * 4 + g8 + 32 * k;       // 0..127
            const size_t fidx = (size_t)row * (DEL / 4) + (size_t)c * 8 + f;
            a[k] = reinterpret_cast<const float4*>(imgs )[fidx];
            w[k] = reinterpret_cast<const float4*>(imgsw)[fidx];
            t[k] = reinterpret_cast<const float4*>(tgt  )[fidx];
        }
    };

    auto sts_chunk = [&](const float4* a, const float4* w, const float4* t, int st) {
        #pragma unroll
        for (int k = 0; k < 4; k++) {
            const int row = warp * 4 + g8 + 32 * k;
            float4 d4 = make_float4(w[k].x - a[k].x, w[k].y - a[k].y,
                                    w[k].z - a[k].z, w[k].w - a[k].w);
            sx[k] += d4.x * d4.x + d4.y * d4.y + d4.z * d4.z + d4.w * d4.w;
            sy[k] += t[k].x * t[k].x + t[k].y * t[k].y
                   + t[k].z * t[k].z + t[k].w * t[k].w;
            sA[st][row * SW + f * 2    ] = pack_bf16x2(d4.x, d4.y);
            sA[st][row * SW + f * 2 + 1] = pack_bf16x2(d4.z, d4.w);
            sB[st][row * SW + f * 2    ] = pack_bf16x2(t[k].x, t[k].y);
            sB[st][row * SW + f * 2 + 1] = pack_bf16x2(t[k].z, t[k].w);
        }
    };

    auto mma_buf = [&](int st) {
        #pragma unroll
        for (int kk = 0; kk < 2; kk++) {
            uint32_t A0[2], A1[2], A2[2], A3[2];
            #pragma unroll
            for (int mt = 0; mt < 2; mt++) {
                const int row = m0 + mt * 16 + g;
                A0[mt] = sA[st][ row      * SW + kk * 8 + tg    ];
                A1[mt] = sA[st][(row + 8) * SW + kk * 8 + tg    ];
                A2[mt] = sA[st][ row      * SW + kk * 8 + tg + 4];
                A3[mt] = sA[st][(row + 8) * SW + kk * 8 + tg + 4];
            }
            #pragma unroll
            for (int nt = 0; nt < 8; nt++) {
                const int nrow = n0 + nt * 8 + g;
                uint32_t b0 = sB[st][nrow * SW + kk * 8 + tg    ];
                uint32_t b1 = sB[st][nrow * SW + kk * 8 + tg + 4];
                #pragma unroll
                for (int mt = 0; mt < 2; mt++) {
                    asm volatile(
                        "mma.sync.aligned.m16n8k16.row.col.f32.bf16.bf16.f32 "
                        "{%0,%1,%2,%3}, {%4,%5,%6,%7}, {%8,%9}, {%0,%1,%2,%3};"
                        : "+f"(acc[mt][nt][0]), "+f"(acc[mt][nt][1]),
                          "+f"(acc[mt][nt][2]), "+f"(acc[mt][nt][3])
                        : "r"(A0[mt]), "r"(A1[mt]), "r"(A2[mt]), "r"(A3[mt]),
                          "r"(b0), "r"(b1));
                }
            }
        }
    };

    const int c0 = blockIdx.x;
    const int G  = GEMM_GRID;

    // prologue: chunk c0 -> set0 -> buf0 ; chunk c0+G -> set1 (held)
    ldg_chunk(c0, rA0, rW0, rT0);
    if (c0 + G < NCHUNK) ldg_chunk(c0 + G, rA1, rW1, rT1);
    sts_chunk(rA0, rW0, rT0, 0);
    __syncthreads();

    int st = 0;
    for (int c = c0; c < NCHUNK; c += 2 * G) {
        // sub-iter A: current chunk c (buf st); set0 free
        if (c + 2 * G < NCHUNK) ldg_chunk(c + 2 * G, rA0, rW0, rT0);
        mma_buf(st);
        if (c + G < NCHUNK) sts_chunk(rA1, rW1, rT1, st ^ 1);
        __syncthreads();
        st ^= 1;
        if (c + G >= NCHUNK) break;

        // sub-iter B: current chunk c+G (buf st); set1 free
        if (c + 3 * G < NCHUNK) ldg_chunk(c + 3 * G, rA1, rW1, rT1);
        mma_buf(st);
        if (c + 2 * G < NCHUNK) sts_chunk(rA0, rW0, rT0, st ^ 1);
        __syncthreads();
        st ^= 1;
    }

    // write split-K partials
    float* P = g_P[blockIdx.x];
    #pragma unroll
    for (int mt = 0; mt < 2; mt++) {
        #pragma unroll
        for (int nt = 0; nt < 8; nt++) {
            const int row = m0 + mt * 16 + g;
            const int col = n0 + nt * 8 + tg * 2;
            float2* p0 = reinterpret_cast<float2*>(&P[ row      * BSZ + col]);
            float2* p1 = reinterpret_cast<float2*>(&P[(row + 8) * BSZ + col]);
            *p0 = make_float2(acc[mt][nt][0], acc[mt][nt][1]);
            *p1 = make_float2(acc[mt][nt][2], acc[mt][nt][3]);
        }
    }

    // norm partials: 8 lanes (same g8 group) share a row
    #pragma unroll
    for (int k = 0; k < 4; k++) {
        float x = sx[k], y = sy[k];
        x += __shfl_xor_sync(0xFFFFFFFFu, x, 1);
        x += __shfl_xor_sync(0xFFFFFFFFu, x, 2);
        x += __shfl_xor_sync(0xFFFFFFFFu, x, 4);
        y += __shfl_xor_sync(0xFFFFFFFFu, y, 1);
        y += __shfl_xor_sync(0xFFFFFFFFu, y, 2);
        y += __shfl_xor_sync(0xFFFFFFFFu, y, 4);
        if (f == 0) {
            const int row = warp * 4 + g8 + 32 * k;
            g_xp[blockIdx.x][row] = x;
            g_yp[blockIdx.x][row] = y;
        }
    }
}

// ============================================================
// Kernel 2: reduce norm partials
// ============================================================
__global__ void norm_reduce_kernel()
{
    const int t = threadIdx.x;
    float sxv = 0.f, syv = 0.f;
    #pragma unroll 4
    for (int c = 0; c < GEMM_GRID; c++) {
        sxv += g_xp[c][t];
        syv += g_yp[c][t];
    }
    g_x2[t] = sxv;
    g_y2[t] = syv;
}

// ============================================================
// Kernel 3: reduce split-K partials, build C.
// ============================================================
__global__ void __launch_bounds__(512, 1)
cost_kernel()
{
    __shared__ float part[3][BSZ];
    const int i = blockIdx.x;
    const int j = threadIdx.x & 127;
    const int s = threadIdx.x >> 7;            // 0..3

    float sum = 0.f;
    #pragma unroll 4
    for (int c = s; c < GEMM_GRID; c += 4)
        sum += g_P[c][i * BSZ + j];

    if (s > 0) part[s - 1][j] = sum;
    __syncthreads();
    if (s == 0) {
        sum += part[0][j] + part[1][j] + part[2][j];
        const float sq = g_x2[i] + g_y2[j] - 2.f * sum;
        g_C[i * BSZ + j] = sqrtf(fmaxf(sq, 0.f));
    }
}

// ============================================================
// Kernel 4: Sinkhorn (17 us, early exit) — unchanged
// ============================================================
__global__ void __launch_bounds__(512, 1)
sinkhorn_kernel(float* __restrict__ out)
{
    __shared__ __align__(16) float evp[144];   // padded exp(-v)
    __shared__ __align__(16) float eup[144];   // padded exp(-u)
    __shared__ float up[BSZ], vp[BSZ];
    __shared__ float red[16];

    const int t    = threadIdx.x;
    const int lane = t & 31;
    const int q    = lane & 3;
    const int r    = t >> 2;
    const int sidx = r + ((r >> 5) << 2);      // pad-index for publishing

    const float LOGA = -4.852030263919617f;    // log(1/128)
    const float K2   = REGP * 0.6931471805599453f;  // REG * ln2

    float E[32], Et[32];
    float mrow = -1e30f;
    {
        const float4* c4p = reinterpret_cast<const float4*>(g_C + r * BSZ + q * 32);
        #pragma unroll
        for (int k4 = 0; k4 < 8; k4++) {
            float4 c4 = c4p[k4];
            E[k4 * 4 + 0] = c4.x; E[k4 * 4 + 1] = c4.y;
            E[k4 * 4 + 2] = c4.z; E[k4 * 4 + 3] = c4.w;
            mrow = fmaxf(mrow, fmaxf(fmaxf(c4.x, c4.y), fmaxf(c4.z, c4.w)));
        }
    }
    mrow = fmaxf(mrow, __shfl_xor_sync(0xFFFFFFFFu, mrow, 1));
    mrow = fmaxf(mrow, __shfl_xor_sync(0xFFFFFFFFu, mrow, 2));
    #pragma unroll
    for (int k = 0; k < 32; k++) E[k] = __expf(E[k] - mrow);

    float mcol = -1e30f;
    #pragma unroll
    for (int k = 0; k < 32; k++) {
        float cvv = g_C[(q * 32 + k) * BSZ + r];
        Et[k] = cvv;
        mcol = fmaxf(mcol, cvv);
    }
    mcol = fmaxf(mcol, __shfl_xor_sync(0xFFFFFFFFu, mcol, 1));
    mcol = fmaxf(mcol, __shfl_xor_sync(0xFFFFFFFFu, mcol, 2));
    #pragma unroll
    for (int k = 0; k < 32; k++) Et[k] = __expf(Et[k] - mcol);

    const float cu = REGP * (LOGA - mrow);
    const float cv = REGP * (LOGA - mcol);

    float ureg = 0.f, vreg = 0.f;

    if (t < 144) { evp[t] = 1.f; eup[t] = 1.f; }
    __syncthreads();

    const float4* evq = reinterpret_cast<const float4*>(evp + q * 36);
    const float4* euq = reinterpret_cast<const float4*>(eup + q * 36);

    bool done = false;
    for (int it = 0; it < NUM_ITER && !done; ++it) {
        float s0 = 0.f, s1 = 0.f, s2 = 0.f, s3 = 0.f;
        #pragma unroll
        for (int k4 = 0; k4 < 8; k4++) {
            float4 w = evq[k4];
            s0 = fmaf(E[k4 * 4 + 0], w.x, s0);
            s1 = fmaf(E[k4 * 4 + 1], w.y, s1);
            s2 = fmaf(E[k4 * 4 + 2], w.z, s2);
            s3 = fmaf(E[k4 * 4 + 3], w.w, s3);
        }
        float S = (s0 + s1) + (s2 + s3);
        S += __shfl_xor_sync(0xFFFFFFFFu, S, 1);
        S += __shfl_xor_sync(0xFFFFFFFFu, S, 2);
        float un = fmaf(REGP, ureg, cu) - K2 * __log2f(S);
        eup[sidx] = __expf(-un);
        float du = fabsf(un - ureg);
        ureg = un;
        int convu = __syncthreads_and(du < 2.5e-7f);

        float t0 = 0.f, t1 = 0.f, t2 = 0.f, t3 = 0.f;
        #pragma unroll
        for (int k4 = 0; k4 < 8; k4++) {
            float4 w = euq[k4];
            t0 = fmaf(Et[k4 * 4 + 0], w.x, t0);
            t1 = fmaf(Et[k4 * 4 + 1], w.y, t1);
            t2 = fmaf(Et[k4 * 4 + 2], w.z, t2);
            t3 = fmaf(Et[k4 * 4 + 3], w.w, t3);
        }
        float T = (t0 + t1) + (t2 + t3);
        T += __shfl_xor_sync(0xFFFFFFFFu, T, 1);
        T += __shfl_xor_sync(0xFFFFFFFFu, T, 2);
        float vn = fmaf(REGP, vreg, cv) - K2 * __log2f(T);
        evp[sidx] = __expf(-vn);
        float dv = fabsf(vn - vreg);
        vreg = vn;
        int convv = __syncthreads_and(dv < 2.5e-7f);

        done = (it >= 11) && (convu != 0) && (convv != 0);
    }

    up[r] = ureg;
    vp[r] = vreg;
    __syncthreads();
    float s = (t < BSZ) ? (up[t] + vp[t]) : 0.f;
    #pragma unroll
    for (int o = 16; o > 0; o >>= 1)
        s += __shfl_xor_sync(0xFFFFFFFFu, s, o);
    if (lane == 0) red[t >> 5] = s;
    __syncthreads();
    if (t == 0)
        out[0] = (red[0] + red[1] + red[2] + red[3]) * (1.0f / BSZ);
}

// ============================================================
extern "C" void kernel_launch(void* const* d_in, const int* in_sizes, int n_in,
                              void* d_out, int out_size)
{
    const float* imgs  = (const float*)d_in[0];
    const float* imgsw = (const float*)d_in[1];
    const float* tgt   = (const float*)d_in[2];
    float* out = (float*)d_out;

    gemm_kernel<<<GEMM_GRID, 256>>>(imgs, imgsw, tgt);
    norm_reduce_kernel<<<1, BSZ>>>();
    cost_kernel<<<BSZ, 512>>>();
    sinkhorn_kernel<<<1, 512>>>(out);
}

// round 8
// speedup vs baseline: 4.0994x; 1.0146x over previous
#include <cuda_runtime.h>
#include <cuda_bf16.h>
#include <cstdint>

#define GEMM_GRID 148
#define BSZ       128
#define DEL       196608          // 3*256*256
#define KC        32              // K elements per chunk
#define NCHUNK    (DEL / KC)      // 6144
#define REGP      0.01f
#define NUM_ITER  100
#define SW        20              // smem row stride in uint32 words (40 bf16)

// -------- deterministic global scratch (no allocations allowed) --------
__device__ float g_P [GEMM_GRID][BSZ * BSZ]; // split-K partial dot products
__device__ float g_xp[GEMM_GRID][BSZ];       // partial ||delta||^2
__device__ float g_yp[GEMM_GRID][BSZ];       // partial ||target||^2
__device__ float g_x2[BSZ];
__device__ float g_y2[BSZ];
__device__ float g_C [BSZ * BSZ];            // cost matrix

__device__ __forceinline__ uint32_t pack_bf16x2(float lo, float hi) {
    __nv_bfloat162 h = __floats2bfloat162_rn(lo, hi);
    return *reinterpret_cast<uint32_t*>(&h);
}

// ============================================================
// Kernel 1: split-K GEMM (bf16 HMMA) + fp32 row norms.
//   512 threads / 16 warps (4 per SMSP) for latency slack.
//   2-deep register prefetch + double-buffered smem, 1 BAR/chunk:
//     iter k: LDG(k+2) ; MMA(buf=chunk k) ; STS(k+1 -> buf^1) ; BAR
// ============================================================
__global__ void __launch_bounds__(512, 1)
gemm_kernel(const float* __restrict__ imgs,
            const float* __restrict__ imgsw,
            const float* __restrict__ tgt)
{
    __shared__ uint32_t sA[2][BSZ * SW];
    __shared__ uint32_t sB[2][BSZ * SW];

    const int tid  = threadIdx.x;
    const int lane = tid & 31;
    const int warp = tid >> 5;           // 0..15

    // loader mapping: 8 lanes cover one row's 128B; warp covers 8 rows
    const int g8 = lane >> 3;            // 0..3
    const int f  = lane & 7;             // float4 index in row chunk

    // mma mapping: 4x4 warp grid of 32x32 tiles
    const int m0 = (warp & 3) * 32;
    const int n0 = (warp >> 2) * 32;
    const int g  = lane >> 2;
    const int tg = lane & 3;

    float acc[2][4][4];
    #pragma unroll
    for (int a = 0; a < 2; a++)
        #pragma unroll
        for (int b = 0; b < 4; b++)
            #pragma unroll
            for (int cc = 0; cc < 4; cc++) acc[a][b][cc] = 0.f;

    float sx[2] = {0.f, 0.f};
    float sy[2] = {0.f, 0.f};

    float4 rA0[2], rW0[2], rT0[2];       // prefetch set 0 (24 floats)
    float4 rA1[2], rW1[2], rT1[2];       // prefetch set 1

    auto ldg_chunk = [&](int c, float4* a, float4* w, float4* t) {
        #pragma unroll
        for (int k = 0; k < 2; k++) {
            const int row = warp * 8 + g8 + 4 * k;        // 0..127
            const size_t fidx = (size_t)row * (DEL / 4) + (size_t)c * 8 + f;
            a[k] = reinterpret_cast<const float4*>(imgs )[fidx];
            w[k] = reinterpret_cast<const float4*>(imgsw)[fidx];
            t[k] = reinterpret_cast<const float4*>(tgt  )[fidx];
        }
    };

    auto sts_chunk = [&](const float4* a, const float4* w, const float4* t, int st) {
        #pragma unroll
        for (int k = 0; k < 2; k++) {
            const int row = warp * 8 + g8 + 4 * k;
            float4 d4 = make_float4(w[k].x - a[k].x, w[k].y - a[k].y,
                                    w[k].z - a[k].z, w[k].w - a[k].w);
            sx[k] += d4.x * d4.x + d4.y * d4.y + d4.z * d4.z + d4.w * d4.w;
            sy[k] += t[k].x * t[k].x + t[k].y * t[k].y
                   + t[k].z * t[k].z + t[k].w * t[k].w;
            sA[st][row * SW + f * 2    ] = pack_bf16x2(d4.x, d4.y);
            sA[st][row * SW + f * 2 + 1] = pack_bf16x2(d4.z, d4.w);
            sB[st][row * SW + f * 2    ] = pack_bf16x2(t[k].x, t[k].y);
            sB[st][row * SW + f * 2 + 1] = pack_bf16x2(t[k].z, t[k].w);
        }
    };

    auto mma_buf = [&](int st) {
        #pragma unroll
        for (int kk = 0; kk < 2; kk++) {
            uint32_t A0[2], A1[2], A2[2], A3[2];
            #pragma unroll
            for (int mt = 0; mt < 2; mt++) {
                const int row = m0 + mt * 16 + g;
                A0[mt] = sA[st][ row      * SW + kk * 8 + tg    ];
                A1[mt] = sA[st][(row + 8) * SW + kk * 8 + tg    ];
                A2[mt] = sA[st][ row      * SW + kk * 8 + tg + 4];
                A3[mt] = sA[st][(row + 8) * SW + kk * 8 + tg + 4];
            }
            #pragma unroll
            for (int nt = 0; nt < 4; nt++) {
                const int nrow = n0 + nt * 8 + g;
                uint32_t b0 = sB[st][nrow * SW + kk * 8 + tg    ];
                uint32_t b1 = sB[st][nrow * SW + kk * 8 + tg + 4];
                #pragma unroll
                for (int mt = 0; mt < 2; mt++) {
                    asm volatile(
                        "mma.sync.aligned.m16n8k16.row.col.f32.bf16.bf16.f32 "
                        "{%0,%1,%2,%3}, {%4,%5,%6,%7}, {%8,%9}, {%0,%1,%2,%3};"
                        : "+f"(acc[mt][nt][0]), "+f"(acc[mt][nt][1]),
                          "+f"(acc[mt][nt][2]), "+f"(acc[mt][nt][3])
                        : "r"(A0[mt]), "r"(A1[mt]), "r"(A2[mt]), "r"(A3[mt]),
                          "r"(b0), "r"(b1));
                }
            }
        }
    };

    const int c0 = blockIdx.x;
    const int G  = GEMM_GRID;

    // prologue
    ldg_chunk(c0, rA0, rW0, rT0);
    if (c0 + G < NCHUNK) ldg_chunk(c0 + G, rA1, rW1, rT1);
    sts_chunk(rA0, rW0, rT0, 0);
    __syncthreads();

    int st = 0;
    for (int c = c0; c < NCHUNK; c += 2 * G) {
        if (c + 2 * G < NCHUNK) ldg_chunk(c + 2 * G, rA0, rW0, rT0);
        mma_buf(st);
        if (c + G < NCHUNK) sts_chunk(rA1, rW1, rT1, st ^ 1);
        __syncthreads();
        st ^= 1;
        if (c + G >= NCHUNK) break;

        if (c + 3 * G < NCHUNK) ldg_chunk(c + 3 * G, rA1, rW1, rT1);
        mma_buf(st);
        if (c + 2 * G < NCHUNK) sts_chunk(rA0, rW0, rT0, st ^ 1);
        __syncthreads();
        st ^= 1;
    }

    // write split-K partials (each warp its 32x32 tile)
    float* P = g_P[blockIdx.x];
    #pragma unroll
    for (int mt = 0; mt < 2; mt++) {
        #pragma unroll
        for (int nt = 0; nt < 4; nt++) {
            const int row = m0 + mt * 16 + g;
            const int col = n0 + nt * 8 + tg * 2;
            float2* p0 = reinterpret_cast<float2*>(&P[ row      * BSZ + col]);
            float2* p1 = reinterpret_cast<float2*>(&P[(row + 8) * BSZ + col]);
            *p0 = make_float2(acc[mt][nt][0], acc[mt][nt][1]);
            *p1 = make_float2(acc[mt][nt][2], acc[mt][nt][3]);
        }
    }

    // norm partials: 8 lanes (f=0..7) share a row
    #pragma unroll
    for (int k = 0; k < 2; k++) {
        float x = sx[k], y = sy[k];
        x += __shfl_xor_sync(0xFFFFFFFFu, x, 1);
        x += __shfl_xor_sync(0xFFFFFFFFu, x, 2);
        x += __shfl_xor_sync(0xFFFFFFFFu, x, 4);
        y += __shfl_xor_sync(0xFFFFFFFFu, y, 1);
        y += __shfl_xor_sync(0xFFFFFFFFu, y, 2);
        y += __shfl_xor_sync(0xFFFFFFFFu, y, 4);
        if (f == 0) {
            const int row = warp * 8 + g8 + 4 * k;
            g_xp[blockIdx.x][row] = x;
            g_yp[blockIdx.x][row] = y;
        }
    }
}

// ============================================================
// Kernel 2: reduce norm partials
// ============================================================
__global__ void norm_reduce_kernel()
{
    const int t = threadIdx.x;
    float sxv = 0.f, syv = 0.f;
    #pragma unroll 4
    for (int c = 0; c < GEMM_GRID; c++) {
        sxv += g_xp[c][t];
        syv += g_yp[c][t];
    }
    g_x2[t] = sxv;
    g_y2[t] = syv;
}

// ============================================================
// Kernel 3: reduce split-K partials, build C.
// ============================================================
__global__ void __launch_bounds__(512, 1)
cost_kernel()
{
    __shared__ float part[3][BSZ];
    const int i = blockIdx.x;
    const int j = threadIdx.x & 127;
    const int s = threadIdx.x >> 7;            // 0..3

    float sum = 0.f;
    #pragma unroll 4
    for (int c = s; c < GEMM_GRID; c += 4)
        sum += g_P[c][i * BSZ + j];

    if (s > 0) part[s - 1][j] = sum;
    __syncthreads();
    if (s == 0) {
        sum += part[0][j] + part[1][j] + part[2][j];
        const float sq = g_x2[i] + g_y2[j] - 2.f * sum;
        g_C[i * BSZ + j] = sqrtf(fmaxf(sq, 0.f));
    }
}

// ============================================================
// Kernel 4: Sinkhorn (17 us, early exit) — unchanged
// ============================================================
__global__ void __launch_bounds__(512, 1)
sinkhorn_kernel(float* __restrict__ out)
{
    __shared__ __align__(16) float evp[144];   // padded exp(-v)
    __shared__ __align__(16) float eup[144];   // padded exp(-u)
    __shared__ float up[BSZ], vp[BSZ];
    __shared__ float red[16];

    const int t    = threadIdx.x;
    const int lane = t & 31;
    const int q    = lane & 3;
    const int r    = t >> 2;
    const int sidx = r + ((r >> 5) << 2);      // pad-index for publishing

    const float LOGA = -4.852030263919617f;    // log(1/128)
    const float K2   = REGP * 0.6931471805599453f;  // REG * ln2

    float E[32], Et[32];
    float mrow = -1e30f;
    {
        const float4* c4p = reinterpret_cast<const float4*>(g_C + r * BSZ + q * 32);
        #pragma unroll
        for (int k4 = 0; k4 < 8; k4++) {
            float4 c4 = c4p[k4];
            E[k4 * 4 + 0] = c4.x; E[k4 * 4 + 1] = c4.y;
            E[k4 * 4 + 2] = c4.z; E[k4 * 4 + 3] = c4.w;
            mrow = fmaxf(mrow, fmaxf(fmaxf(c4.x, c4.y), fmaxf(c4.z, c4.w)));
        }
    }
    mrow = fmaxf(mrow, __shfl_xor_sync(0xFFFFFFFFu, mrow, 1));
    mrow = fmaxf(mrow, __shfl_xor_sync(0xFFFFFFFFu, mrow, 2));
    #pragma unroll
    for (int k = 0; k < 32; k++) E[k] = __expf(E[k] - mrow);

    float mcol = -1e30f;
    #pragma unroll
    for (int k = 0; k < 32; k++) {
        float cvv = g_C[(q * 32 + k) * BSZ + r];
        Et[k] = cvv;
        mcol = fmaxf(mcol, cvv);
    }
    mcol = fmaxf(mcol, __shfl_xor_sync(0xFFFFFFFFu, mcol, 1));
    mcol = fmaxf(mcol, __shfl_xor_sync(0xFFFFFFFFu, mcol, 2));
    #pragma unroll
    for (int k = 0; k < 32; k++) Et[k] = __expf(Et[k] - mcol);

    const float cu = REGP * (LOGA - mrow);
    const float cv = REGP * (LOGA - mcol);

    float ureg = 0.f, vreg = 0.f;

    if (t < 144) { evp[t] = 1.f; eup[t] = 1.f; }
    __syncthreads();

    const float4* evq = reinterpret_cast<const float4*>(evp + q * 36);
    const float4* euq = reinterpret_cast<const float4*>(eup + q * 36);

    bool done = false;
    for (int it = 0; it < NUM_ITER && !done; ++it) {
        float s0 = 0.f, s1 = 0.f, s2 = 0.f, s3 = 0.f;
        #pragma unroll
        for (int k4 = 0; k4 < 8; k4++) {
            float4 w = evq[k4];
            s0 = fmaf(E[k4 * 4 + 0], w.x, s0);
            s1 = fmaf(E[k4 * 4 + 1], w.y, s1);
            s2 = fmaf(E[k4 * 4 + 2], w.z, s2);
            s3 = fmaf(E[k4 * 4 + 3], w.w, s3);
        }
        float S = (s0 + s1) + (s2 + s3);
        S += __shfl_xor_sync(0xFFFFFFFFu, S, 1);
        S += __shfl_xor_sync(0xFFFFFFFFu, S, 2);
        float un = fmaf(REGP, ureg, cu) - K2 * __log2f(S);
        eup[sidx] = __expf(-un);
        float du = fabsf(un - ureg);
        ureg = un;
        int convu = __syncthreads_and(du < 2.5e-7f);

        float t0 = 0.f, t1 = 0.f, t2 = 0.f, t3 = 0.f;
        #pragma unroll
        for (int k4 = 0; k4 < 8; k4++) {
            float4 w = euq[k4];
            t0 = fmaf(Et[k4 * 4 + 0], w.x, t0);
            t1 = fmaf(Et[k4 * 4 + 1], w.y, t1);
            t2 = fmaf(Et[k4 * 4 + 2], w.z, t2);
            t3 = fmaf(Et[k4 * 4 + 3], w.w, t3);
        }
        float T = (t0 + t1) + (t2 + t3);
        T += __shfl_xor_sync(0xFFFFFFFFu, T, 1);
        T += __shfl_xor_sync(0xFFFFFFFFu, T, 2);
        float vn = fmaf(REGP, vreg, cv) - K2 * __log2f(T);
        evp[sidx] = __expf(-vn);
        float dv = fabsf(vn - vreg);
        vreg = vn;
        int convv = __syncthreads_and(dv < 2.5e-7f);

        done = (it >= 11) && (convu != 0) && (convv != 0);
    }

    up[r] = ureg;
    vp[r] = vreg;
    __syncthreads();
    float s = (t < BSZ) ? (up[t] + vp[t]) : 0.f;
    #pragma unroll
    for (int o = 16; o > 0; o >>= 1)
        s += __shfl_xor_sync(0xFFFFFFFFu, s, o);
    if (lane == 0) red[t >> 5] = s;
    __syncthreads();
    if (t == 0)
        out[0] = (red[0] + red[1] + red[2] + red[3]) * (1.0f / BSZ);
}

// ============================================================
extern "C" void kernel_launch(void* const* d_in, const int* in_sizes, int n_in,
                              void* d_out, int out_size)
{
    const float* imgs  = (const float*)d_in[0];
    const float* imgsw = (const float*)d_in[1];
    const float* tgt   = (const float*)d_in[2];
    float* out = (float*)d_out;

    gemm_kernel<<<GEMM_GRID, 512>>>(imgs, imgsw, tgt);
    norm_reduce_kernel<<<1, BSZ>>>();
    cost_kernel<<<BSZ, 512>>>();
    sinkhorn_kernel<<<1, 512>>>(out);
}